// round 1
// baseline (speedup 1.0000x reference)
#include <cuda_runtime.h>
#include <cstdint>

// Problem shape (all compile-time, all powers of 2):
//   L=8, B=2, H=8, S_FULL=4096, S_NEW=4, D=128, fp32
// Inputs (metadata order): past_k, past_v, new_k, new_v (f32), target_positions (i32, [B,1])
// Output: stack((present_k, present_v)) -> (2, L, B, H, S_FULL, D) f32
//
// Pure bandwidth problem: 512MB in + 512MB out. One float4 per thread,
// fully coalesced; "new" window selected with one unsigned compare.

static constexpr unsigned D4      = 128 / 4;      // 32 float4 per row
static constexpr unsigned S_FULL  = 4096;
static constexpr unsigned S_NEW   = 4;
static constexpr unsigned H       = 8;
static constexpr unsigned B       = 2;
static constexpr unsigned L       = 8;
// float4 count of one full tensor (past_k): L*B*H*S_FULL*D4 = 2^24
static constexpr unsigned PAST_F4 = L * B * H * S_FULL * D4;   // 16777216
static constexpr unsigned TOTAL_F4 = 2u * PAST_F4;             // 33554432

__global__ void __launch_bounds__(256) kv_scatter_copy_kernel(
    const float4* __restrict__ pk,
    const float4* __restrict__ pv,
    const float4* __restrict__ nk,
    const float4* __restrict__ nv,
    const int*    __restrict__ tpos,
    float4*       __restrict__ out)
{
    unsigned i = blockIdx.x * blockDim.x + threadIdx.x;   // < TOTAL_F4 (fits u32)

    // Decompose: i = (((kv*L + l)*B + b)*H + h)*S_FULL + s)*D4 + d4
    unsigned d4 = i & (D4 - 1);
    unsigned s  = (i >> 5) & (S_FULL - 1);
    unsigned r  = i >> 17;                 // h | b | l | kv
    unsigned h  = r & (H - 1);
    unsigned b  = (r >> 3) & (B - 1);
    unsigned l  = (r >> 4) & (L - 1);
    unsigned kv = r >> 7;

    unsigned off = (unsigned)__ldg(&tpos[b]);   // target_positions[b,0]

    float4 val;
    if (s - off < S_NEW) {
        // New-token window: index into (L,B,H,S_NEW,D)
        unsigned sidx = ((((l * B + b) * H + h) * S_NEW + (s - off)) * D4) + d4;
        val = kv ? __ldg(&nv[sidx]) : __ldg(&nk[sidx]);
    } else {
        // Past: identical layout to output slab -> lower 24 bits of i
        unsigned sidx = i & (PAST_F4 - 1);
        val = kv ? __ldg(&pv[sidx]) : __ldg(&pk[sidx]);
    }
    out[i] = val;
}

extern "C" void kernel_launch(void* const* d_in, const int* in_sizes, int n_in,
                              void* d_out, int out_size)
{
    const float4* pk = (const float4*)d_in[0];
    const float4* pv = (const float4*)d_in[1];
    const float4* nk = (const float4*)d_in[2];
    const float4* nv = (const float4*)d_in[3];
    const int*    tp = (const int*)d_in[4];
    float4*       out = (float4*)d_out;

    constexpr unsigned threads = 256;
    constexpr unsigned blocks  = TOTAL_F4 / threads;   // 131072
    kv_scatter_copy_kernel<<<blocks, threads>>>(pk, pv, nk, nv, tp, out);
}

// round 2
// speedup vs baseline: 1.0298x; 1.0298x over previous
#include <cuda_runtime.h>
#include <cstdint>

// KV-cache scatter-copy, pure HBM streaming.
//   L=8, B=2, H=8, S_FULL=4096, S_NEW=4, D=128, fp32
// out (2,L,B,H,S_FULL,D) = stack(past_k, past_v) with 4-row window per (l,b,h)
// overwritten from new_k/new_v at target_positions[b].
//
// R2: 4x float4 per thread, front-batched loads (MLP_p1=4), block-uniform
// source selection (kv/l/b/h constant within a 1024-float4 block tile).

static constexpr unsigned D4       = 32;                       // float4 per row
static constexpr unsigned S_FULL   = 4096;
static constexpr unsigned S_NEW    = 4;
static constexpr unsigned H        = 8;
static constexpr unsigned B        = 2;
static constexpr unsigned L        = 8;
static constexpr unsigned PAST_F4  = L * B * H * S_FULL * D4;  // 2^24
static constexpr unsigned TOTAL_F4 = 2u * PAST_F4;             // 2^25

static constexpr unsigned TPB  = 256;
static constexpr unsigned U    = 4;
static constexpr unsigned TILE = TPB * U;                      // 1024 float4 per block

__global__ void __launch_bounds__(TPB) kv_scatter_copy_u4(
    const float4* __restrict__ pk,
    const float4* __restrict__ pv,
    const float4* __restrict__ nk,
    const float4* __restrict__ nv,
    const int*    __restrict__ tpos,
    float4*       __restrict__ out)
{
    const unsigned base = blockIdx.x * TILE + threadIdx.x;

    // Bits >= 17 are uniform across the whole block (TILE = 2^10).
    const unsigned r  = base >> 17;           // h | b | l | kv
    const unsigned h  = r & (H - 1);
    const unsigned b  = (r >> 3) & (B - 1);
    const unsigned l  = (r >> 4) & (L - 1);
    const unsigned kv = r >> 7;

    const unsigned off = (unsigned)__ldg(&tpos[b]);

    const float4* __restrict__ past = kv ? pv : pk;     // same layout as out slab
    const float4* __restrict__ nw   = (kv ? nv : nk)
                                      + (((l * B + b) * H + h) * S_NEW) * D4;

    float4 v[U];
#pragma unroll
    for (unsigned u = 0; u < U; u++) {
        const unsigned i  = base + u * TPB;
        const unsigned s  = (i >> 5) & (S_FULL - 1);
        const unsigned d4 = i & (D4 - 1);
        const unsigned w  = s - off;                    // unsigned wrap: in-window iff < S_NEW
        const float4* p = (w < S_NEW) ? (nw + w * D4 + d4)
                                      : (past + (i & (PAST_F4 - 1)));
        v[u] = __ldg(p);
    }
#pragma unroll
    for (unsigned u = 0; u < U; u++) {
        __stcs(&out[base + u * TPB], v[u]);             // streaming store, skip L2 retention
    }
}

extern "C" void kernel_launch(void* const* d_in, const int* in_sizes, int n_in,
                              void* d_out, int out_size)
{
    const float4* pk = (const float4*)d_in[0];
    const float4* pv = (const float4*)d_in[1];
    const float4* nk = (const float4*)d_in[2];
    const float4* nv = (const float4*)d_in[3];
    const int*    tp = (const int*)d_in[4];
    float4*       out = (float4*)d_out;

    constexpr unsigned blocks = TOTAL_F4 / TILE;        // 32768
    kv_scatter_copy_u4<<<blocks, TPB>>>(pk, pv, nk, nv, tp, out);
}

// round 3
// speedup vs baseline: 1.0406x; 1.0105x over previous
#include <cuda_runtime.h>
#include <cstdint>

// KV-cache scatter-copy, pure HBM streaming.
//   L=8, B=2, H=8, S_FULL=4096, S_NEW=4, D=128, fp32
// out (2,L,B,H,S_FULL,D) = stack(past_k, past_v) with a 4-row window per
// (l,b,h) overwritten from new_k/new_v at target_positions[b].
//
// R3: 8x float4 per thread (front-batched -> MLP_p1=8), streaming loads
// (.cs) on the read-once past data, streaming stores, 2048-f4 block tile
// (kv/l/b/h still block-uniform since 2^11 < 2^17).

static constexpr unsigned D4       = 32;                       // float4 per row
static constexpr unsigned S_FULL   = 4096;
static constexpr unsigned S_NEW    = 4;
static constexpr unsigned H        = 8;
static constexpr unsigned B        = 2;
static constexpr unsigned L        = 8;
static constexpr unsigned PAST_F4  = L * B * H * S_FULL * D4;  // 2^24
static constexpr unsigned TOTAL_F4 = 2u * PAST_F4;             // 2^25

static constexpr unsigned TPB  = 256;
static constexpr unsigned U    = 8;
static constexpr unsigned TILE = TPB * U;                      // 2048 float4 per block

__global__ void __launch_bounds__(TPB) kv_scatter_copy_u8(
    const float4* __restrict__ pk,
    const float4* __restrict__ pv,
    const float4* __restrict__ nk,
    const float4* __restrict__ nv,
    const int*    __restrict__ tpos,
    float4*       __restrict__ out)
{
    const unsigned base = blockIdx.x * TILE + threadIdx.x;

    // Bits >= 17 are uniform across the whole block (TILE = 2^11).
    const unsigned r  = base >> 17;           // h | b | l | kv
    const unsigned h  = r & (H - 1);
    const unsigned b  = (r >> 3) & (B - 1);
    const unsigned l  = (r >> 4) & (L - 1);
    const unsigned kv = r >> 7;

    const unsigned off = (unsigned)__ldg(&tpos[b]);

    const float4* __restrict__ past = kv ? pv : pk;     // same layout as out slab
    const float4* __restrict__ nw   = (kv ? nv : nk)
                                      + (((l * B + b) * H + h) * S_NEW) * D4;

    float4 v[U];
#pragma unroll
    for (unsigned u = 0; u < U; u++) {
        const unsigned i  = base + u * TPB;
        const unsigned s  = (i >> 5) & (S_FULL - 1);
        const unsigned d4 = i & (D4 - 1);
        const unsigned w  = s - off;                    // unsigned wrap: in-window iff < S_NEW
        if (w < S_NEW) {
            v[u] = __ldg(nw + w * D4 + d4);             // tiny window: keep in L2
        } else {
            v[u] = __ldcs(past + (i & (PAST_F4 - 1)));  // read-once bulk: streaming
        }
    }
#pragma unroll
    for (unsigned u = 0; u < U; u++) {
        __stcs(&out[base + u * TPB], v[u]);             // streaming store
    }
}

extern "C" void kernel_launch(void* const* d_in, const int* in_sizes, int n_in,
                              void* d_out, int out_size)
{
    const float4* pk = (const float4*)d_in[0];
    const float4* pv = (const float4*)d_in[1];
    const float4* nk = (const float4*)d_in[2];
    const float4* nv = (const float4*)d_in[3];
    const int*    tp = (const int*)d_in[4];
    float4*       out = (float4*)d_out;

    constexpr unsigned blocks = TOTAL_F4 / TILE;        // 16384
    kv_scatter_copy_u8<<<blocks, TPB>>>(pk, pv, nk, nv, tp, out);
}